// round 2
// baseline (speedup 1.0000x reference)
#include <cuda_runtime.h>
#include <cstdint>
#include <cstddef>
#include <math.h>

// Problem dims
#define BATCH 256
#define Z_DIM 256
#define T_DIM 512
#define ACT_E 256
#define CF    1024
#define N_ACT 64
#define STEPS 64
#define G4    (4*CF)          // 4096

// ---------------- scratch (device globals; no allocation allowed) ----------
__device__ float d_t_rec [BATCH*T_DIM];
__device__ float d_base_a[BATCH*G4];
__device__ float d_base_t[BATCH*G4];
__device__ float d_Ga    [N_ACT*G4];
__device__ float d_Gt    [N_ACT*G4];
__device__ float d_wcol  [G4];
__device__ float d_h_a   [BATCH*CF];
__device__ float d_c_a   [BATCH*CF];
__device__ float d_h_t   [BATCH*CF];
__device__ float d_c_t   [BATCH*CF];
__device__ float d_gates [BATCH*G4];
__device__ float d_hid_part[4*BATCH*(CF/2)];
__device__ float d_ts    [BATCH];
__device__ int   d_act   [BATCH];

__device__ __forceinline__ float sigf(float x) { return 1.0f / (1.0f + expf(-x)); }

// ---------------- init: zero recurrent state, act=EOT(63), extract ts col --
__global__ void init_kernel(const float* __restrict__ Wih_t)
{
    int i = blockIdx.x * blockDim.x + threadIdx.x;
    if (i < BATCH*CF) {
        d_h_a[i] = 0.f; d_c_a[i] = 0.f; d_h_t[i] = 0.f; d_c_t[i] = 0.f;
    }
    if (i < BATCH) { d_ts[i] = 0.f; d_act[i] = N_ACT - 1; }
    if (i < G4)    { d_wcol[i] = Wih_t[(size_t)i * (T_DIM + ACT_E + 1) + (T_DIM + ACT_E)]; }
}

// ---------------- generic fp32 GEMM: C = A[M,K] * B[N,K]^T + epilogue ------
// Row-major A (lda), row-major B (ldb, k contiguous), row-major C (ldc).
// Double-buffered smem, register-staged global prefetch.
// blockIdx.z = split-K slice: offsets A,B by z*K columns, C by z*M*ldc.
// Epilogue (all nullable): + bias0[n] + bias1[n] + addRow[m,n]
//                          + gTab[gIdx[m], n] + tsvec[m]*tscol[n]; optional relu.
template<int BM, int BN, int BK, int TM, int TN>
__global__ void __launch_bounds__((BM/TM)*(BN/TN))
gemm_kernel(const float* __restrict__ A, int lda,
            const float* __restrict__ B, int ldb,
            float* __restrict__ C, int ldc,
            int M, int N, int K,
            const float* __restrict__ bias0, const float* __restrict__ bias1, int relu,
            const float* __restrict__ addRow, int ldAdd,
            const float* __restrict__ gTab, const int* __restrict__ gIdx, int ldG,
            const float* __restrict__ tsvec, const float* __restrict__ tscol)
{
    constexpr int THREADS = (BM/TM)*(BN/TN);
    constexpr int AV  = BM*BK/(4*THREADS);   // float4 loads per thread (A)
    constexpr int BV  = BN*BK/(4*THREADS);   // float4 loads per thread (B vector path)
    constexpr int BSC = BN*BK/THREADS;       // scalar loads per thread (B scalar path)
    static_assert(TM == 4 && (TN % 4) == 0, "tile config");

    __shared__ float As[2][BK][BM];
    __shared__ float Bs[2][BK][BN];

    const int tid = threadIdx.x;
    const int m0  = blockIdx.y * BM;
    const int n0  = blockIdx.x * BN;
    const int kz  = blockIdx.z;
    A += (size_t)kz * K;
    B += (size_t)kz * K;
    C += (size_t)kz * M * (size_t)ldc;

    const bool bvec = ((ldb & 3) == 0) && ((((size_t)B) & 15) == 0);

    const int tm0 = (tid / (BN/TN)) * TM;
    const int tn0 = (tid % (BN/TN)) * TN;

    float4 ra[AV];
    float4 rb[BV];
    float  rbs[BSC];
    float  acc[TM][TN];
    #pragma unroll
    for (int i = 0; i < TM; ++i)
        #pragma unroll
        for (int j = 0; j < TN; ++j) acc[i][j] = 0.f;

    const int nt = K / BK;

    // ---- prologue: fetch tile 0 ----
    {
        const int kk = 0;
        #pragma unroll
        for (int r = 0; r < AV; ++r) {
            int idx = tid + r*THREADS; int m = idx/(BK/4); int kq = idx%(BK/4);
            ra[r] = *reinterpret_cast<const float4*>(A + (size_t)(m0+m)*lda + kk + kq*4);
        }
        if (bvec) {
            #pragma unroll
            for (int r = 0; r < BV; ++r) {
                int idx = tid + r*THREADS; int n = idx/(BK/4); int kq = idx%(BK/4);
                rb[r] = *reinterpret_cast<const float4*>(B + (size_t)(n0+n)*ldb + kk + kq*4);
            }
        } else {
            #pragma unroll
            for (int r = 0; r < BSC; ++r) {
                int idx = tid + r*THREADS; int n = idx/BK; int k = idx%BK;
                rbs[r] = B[(size_t)(n0+n)*ldb + kk + k];
            }
        }
        // store to buffer 0
        #pragma unroll
        for (int r = 0; r < AV; ++r) {
            int idx = tid + r*THREADS; int m = idx/(BK/4); int kq = idx%(BK/4);
            As[0][kq*4+0][m] = ra[r].x; As[0][kq*4+1][m] = ra[r].y;
            As[0][kq*4+2][m] = ra[r].z; As[0][kq*4+3][m] = ra[r].w;
        }
        if (bvec) {
            #pragma unroll
            for (int r = 0; r < BV; ++r) {
                int idx = tid + r*THREADS; int n = idx/(BK/4); int kq = idx%(BK/4);
                Bs[0][kq*4+0][n] = rb[r].x; Bs[0][kq*4+1][n] = rb[r].y;
                Bs[0][kq*4+2][n] = rb[r].z; Bs[0][kq*4+3][n] = rb[r].w;
            }
        } else {
            #pragma unroll
            for (int r = 0; r < BSC; ++r) {
                int idx = tid + r*THREADS; int n = idx/BK; int k = idx%BK;
                Bs[0][k][n] = rbs[r];
            }
        }
    }
    __syncthreads();

    for (int t = 0; t < nt; ++t) {
        const int cur = t & 1;
        const int nxt = (t + 1) & 1;
        // prefetch next tile into registers while computing current
        if (t + 1 < nt) {
            const int kk = (t+1)*BK;
            #pragma unroll
            for (int r = 0; r < AV; ++r) {
                int idx = tid + r*THREADS; int m = idx/(BK/4); int kq = idx%(BK/4);
                ra[r] = *reinterpret_cast<const float4*>(A + (size_t)(m0+m)*lda + kk + kq*4);
            }
            if (bvec) {
                #pragma unroll
                for (int r = 0; r < BV; ++r) {
                    int idx = tid + r*THREADS; int n = idx/(BK/4); int kq = idx%(BK/4);
                    rb[r] = *reinterpret_cast<const float4*>(B + (size_t)(n0+n)*ldb + kk + kq*4);
                }
            } else {
                #pragma unroll
                for (int r = 0; r < BSC; ++r) {
                    int idx = tid + r*THREADS; int n = idx/BK; int k = idx%BK;
                    rbs[r] = B[(size_t)(n0+n)*ldb + kk + k];
                }
            }
        }
        // compute current tile
        #pragma unroll
        for (int k = 0; k < BK; ++k) {
            float a[TM], b[TN];
            *reinterpret_cast<float4*>(a) =
                *reinterpret_cast<const float4*>(&As[cur][k][tm0]);
            #pragma unroll
            for (int q = 0; q < TN/4; ++q)
                *reinterpret_cast<float4*>(&b[q*4]) =
                    *reinterpret_cast<const float4*>(&Bs[cur][k][tn0 + q*4]);
            #pragma unroll
            for (int i = 0; i < TM; ++i)
                #pragma unroll
                for (int j = 0; j < TN; ++j)
                    acc[i][j] = fmaf(a[i], b[j], acc[i][j]);
        }
        // stage next tile into the other smem buffer
        if (t + 1 < nt) {
            #pragma unroll
            for (int r = 0; r < AV; ++r) {
                int idx = tid + r*THREADS; int m = idx/(BK/4); int kq = idx%(BK/4);
                As[nxt][kq*4+0][m] = ra[r].x; As[nxt][kq*4+1][m] = ra[r].y;
                As[nxt][kq*4+2][m] = ra[r].z; As[nxt][kq*4+3][m] = ra[r].w;
            }
            if (bvec) {
                #pragma unroll
                for (int r = 0; r < BV; ++r) {
                    int idx = tid + r*THREADS; int n = idx/(BK/4); int kq = idx%(BK/4);
                    Bs[nxt][kq*4+0][n] = rb[r].x; Bs[nxt][kq*4+1][n] = rb[r].y;
                    Bs[nxt][kq*4+2][n] = rb[r].z; Bs[nxt][kq*4+3][n] = rb[r].w;
                }
            } else {
                #pragma unroll
                for (int r = 0; r < BSC; ++r) {
                    int idx = tid + r*THREADS; int n = idx/BK; int k = idx%BK;
                    Bs[nxt][k][n] = rbs[r];
                }
            }
        }
        __syncthreads();
    }

    // ---- epilogue ----
    #pragma unroll
    for (int i = 0; i < TM; ++i) {
        const int gm = m0 + tm0 + i;
        const float tsm = tsvec ? tsvec[gm] : 0.f;
        const float* addr = addRow ? addRow + (size_t)gm * ldAdd : nullptr;
        const float* gr   = gTab   ? gTab + (size_t)gIdx[gm] * ldG : nullptr;
        #pragma unroll
        for (int j = 0; j < TN; ++j) {
            const int gn = n0 + tn0 + j;
            float v = acc[i][j];
            if (bias0) v += bias0[gn];
            if (bias1) v += bias1[gn];
            if (addr)  v += addr[gn];
            if (gr)    v += gr[gn];
            if (tsvec) v += tsm * tscol[gn];
            if (relu)  v = fmaxf(v, 0.f);
            C[(size_t)gm * ldc + gn] = v;
        }
    }
}

// ---------------- LSTM pointwise: gates[B,4CF] -> h,c [B,CF] --------------
__global__ void lstm_pw_kernel(const float* __restrict__ g,
                               float* __restrict__ h, float* __restrict__ c)
{
    int idx = blockIdx.x * blockDim.x + threadIdx.x;   // BATCH*CF = 262144
    int m = idx >> 10, j = idx & (CF - 1);
    const float* gr = g + ((size_t)m << 12);
    float gi = gr[j], gf = gr[CF + j], gg = gr[2*CF + j], go = gr[3*CF + j];
    float cn = sigf(gf) * c[idx] + sigf(gi) * tanhf(gg);
    c[idx] = cn;
    h[idx] = sigf(go) * tanhf(cn);
}

// ---------------- logits + softmax-out + argmax ----------------------------
// one CTA (256 thr) per batch row: logits = h_a @ W_act^T + b_act
__global__ void logits_kernel(const float* __restrict__ h,
                              const float* __restrict__ W,
                              const float* __restrict__ b,
                              float* __restrict__ out_acts,
                              int* __restrict__ act_idx, int s)
{
    const int row = blockIdx.x, tid = threadIdx.x;
    __shared__ float sh[CF];
    __shared__ float lg[N_ACT];
    __shared__ float stats[2];
    reinterpret_cast<float4*>(sh)[tid] =
        reinterpret_cast<const float4*>(h + (size_t)row * CF)[tid];
    __syncthreads();

    const int j = tid >> 2, q = tid & 3;
    const float4* wr = reinterpret_cast<const float4*>(W + (size_t)j * CF + q * 256);
    const float4* hr = reinterpret_cast<const float4*>(sh) + q * 64;
    float ssum = 0.f;
    #pragma unroll 8
    for (int i = 0; i < 64; ++i) {
        float4 wv = wr[i], hv = hr[i];
        ssum += wv.x*hv.x + wv.y*hv.y + wv.z*hv.z + wv.w*hv.w;
    }
    ssum += __shfl_down_sync(0xffffffffu, ssum, 2);
    ssum += __shfl_down_sync(0xffffffffu, ssum, 1);
    if (q == 0) lg[j] = ssum + b[j];
    __syncthreads();

    if (tid == 0) {
        float mx = lg[0]; int am = 0;
        for (int t = 1; t < N_ACT; ++t) if (lg[t] > mx) { mx = lg[t]; am = t; }
        float sm = 0.f;
        for (int t = 0; t < N_ACT; ++t) sm += expf(lg[t] - mx);
        stats[0] = mx; stats[1] = sm;
        act_idx[row] = am;
    }
    __syncthreads();
    if (tid < N_ACT)
        out_acts[(size_t)row * (STEPS * N_ACT) + s * N_ACT + tid] =
            expf(lg[tid] - stats[0]) / stats[1];
}

// ---------------- ts reduce: combine split-K partials, relu, dot W_ts2 -----
__global__ void tsdot_kernel(const float* __restrict__ part,
                             const float* __restrict__ b1,
                             const float* __restrict__ w2,
                             const float* __restrict__ b2,
                             float* __restrict__ ts,
                             float* __restrict__ out_ts, int s)
{
    const int warp = threadIdx.x >> 5, lane = threadIdx.x & 31;
    const int row = blockIdx.x * 8 + warp;
    const float* p = part + (size_t)row * (CF/2);
    const size_t slice = (size_t)BATCH * (CF/2);
    float acc = 0.f;
    #pragma unroll
    for (int t = 0; t < (CF/2)/32; ++t) {
        int n = lane + t * 32;
        float hv = p[n] + p[slice + n] + p[2*slice + n] + p[3*slice + n] + b1[n];
        hv = fmaxf(hv, 0.f);
        acc += hv * w2[n];
    }
    #pragma unroll
    for (int o = 16; o; o >>= 1) acc += __shfl_down_sync(0xffffffffu, acc, o);
    if (lane == 0) {
        float v = acc + b2[0];
        ts[row] = v;
        out_ts[(size_t)row * STEPS + s] = v;
    }
}

// ---------------- host orchestration ---------------------------------------
using Gemm128 = void(*)(const float*, int, const float*, int, float*, int,
                        int, int, int, const float*, const float*, int,
                        const float*, int, const float*, const int*, int,
                        const float*, const float*);

static inline float* symf(const void* s) { void* p = nullptr; cudaGetSymbolAddress(&p, s); return (float*)p; }

extern "C" void kernel_launch(void* const* d_in, const int* in_sizes, int n_in,
                              void* d_out, int out_size)
{
    const float* z     = (const float*)d_in[0];
    const float* W_z2t = (const float*)d_in[1];
    const float* b_z2t = (const float*)d_in[2];
    const float* E     = (const float*)d_in[3];
    const float* Wih_a = (const float*)d_in[4];
    const float* Whh_a = (const float*)d_in[5];
    const float* bih_a = (const float*)d_in[6];
    const float* bhh_a = (const float*)d_in[7];
    const float* Wih_t = (const float*)d_in[8];
    const float* Whh_t = (const float*)d_in[9];
    const float* bih_t = (const float*)d_in[10];
    const float* bhh_t = (const float*)d_in[11];
    const float* W_act = (const float*)d_in[12];
    const float* b_act = (const float*)d_in[13];
    const float* W_ts1 = (const float*)d_in[14];
    const float* b_ts1 = (const float*)d_in[15];
    const float* W_ts2 = (const float*)d_in[16];
    const float* b_ts2 = (const float*)d_in[17];

    float* out_acts = (float*)d_out;                              // [B, STEPS, N_ACT]
    float* out_ts   = (float*)d_out + (size_t)BATCH*STEPS*N_ACT;  // [B, STEPS]

    float* t_rec  = symf(d_t_rec);
    float* base_a = symf(d_base_a);
    float* base_t = symf(d_base_t);
    float* Ga     = symf(d_Ga);
    float* Gt     = symf(d_Gt);
    float* wcol   = symf(d_wcol);
    float* h_a    = symf(d_h_a);
    float* c_a    = symf(d_c_a);
    float* h_t    = symf(d_h_t);
    float* c_t    = symf(d_c_t);
    float* gates  = symf(d_gates);
    float* hidp   = symf(d_hid_part);
    float* tsb    = symf(d_ts);
    int*   actb   = (int*)symf(d_act);

    auto g128 = gemm_kernel<64,128,16,4,8>;
    auto g64  = gemm_kernel<64,64,16,4,4>;

    // init recurrent state
    init_kernel<<<1024, 256>>>(Wih_t);

    // t_rec = relu(z @ W_z2t^T + b_z2t)      [256,512]
    g128<<<dim3(T_DIM/128, BATCH/64), 256>>>(z, Z_DIM, W_z2t, Z_DIM, t_rec, T_DIM,
        BATCH, T_DIM, Z_DIM, b_z2t, nullptr, 1,
        nullptr, 0, nullptr, nullptr, 0, nullptr, nullptr);
    // base_a = t_rec @ Wih_a[:, :512]^T + bih_a + bhh_a   [256,4096]
    g128<<<dim3(G4/128, BATCH/64), 256>>>(t_rec, T_DIM, Wih_a, T_DIM+ACT_E, base_a, G4,
        BATCH, G4, T_DIM, bih_a, bhh_a, 0,
        nullptr, 0, nullptr, nullptr, 0, nullptr, nullptr);
    // base_t = t_rec @ Wih_t[:, :512]^T + bih_t + bhh_t
    g128<<<dim3(G4/128, BATCH/64), 256>>>(t_rec, T_DIM, Wih_t, T_DIM+ACT_E+1, base_t, G4,
        BATCH, G4, T_DIM, bih_t, bhh_t, 0,
        nullptr, 0, nullptr, nullptr, 0, nullptr, nullptr);
    // Ga = E @ Wih_a[:, 512:768]^T   [64,4096]
    g128<<<dim3(G4/128, 1), 256>>>(E, ACT_E, Wih_a + T_DIM, T_DIM+ACT_E, Ga, G4,
        N_ACT, G4, ACT_E, nullptr, nullptr, 0,
        nullptr, 0, nullptr, nullptr, 0, nullptr, nullptr);
    // Gt = E @ Wih_t[:, 512:768]^T
    g128<<<dim3(G4/128, 1), 256>>>(E, ACT_E, Wih_t + T_DIM, T_DIM+ACT_E+1, Gt, G4,
        N_ACT, G4, ACT_E, nullptr, nullptr, 0,
        nullptr, 0, nullptr, nullptr, 0, nullptr, nullptr);

    for (int s = 0; s < STEPS; ++s) {
        // gates_a = base_a + Ga[act] + h_a @ Whh_a^T
        g128<<<dim3(G4/128, BATCH/64), 256>>>(h_a, CF, Whh_a, CF, gates, G4,
            BATCH, G4, CF, nullptr, nullptr, 0,
            base_a, G4, Ga, actb, G4, nullptr, nullptr);
        lstm_pw_kernel<<<BATCH*CF/256, 256>>>(gates, h_a, c_a);
        // logits -> softmax out, argmax -> actb
        logits_kernel<<<BATCH, 256>>>(h_a, W_act, b_act, out_acts, actb, s);
        // gates_t = base_t + Gt[act] + ts*wcol + h_t @ Whh_t^T
        g128<<<dim3(G4/128, BATCH/64), 256>>>(h_t, CF, Whh_t, CF, gates, G4,
            BATCH, G4, CF, nullptr, nullptr, 0,
            base_t, G4, Gt, actb, G4, tsb, wcol);
        lstm_pw_kernel<<<BATCH*CF/256, 256>>>(gates, h_t, c_t);
        // hidden partials (split-K=4): h_t @ W_ts1^T
        g64<<<dim3((CF/2)/64, BATCH/64, 4), 256>>>(h_t, CF, W_ts1, CF, hidp, CF/2,
            BATCH, CF/2, CF/4, nullptr, nullptr, 0,
            nullptr, 0, nullptr, nullptr, 0, nullptr, nullptr);
        // reduce + relu + dot W_ts2 -> ts
        tsdot_kernel<<<BATCH/8, 256>>>(hidp, b_ts1, W_ts2, b_ts2, tsb, out_ts, s);
    }
    (void)in_sizes; (void)n_in; (void)out_size;
}

// round 4
// speedup vs baseline: 1.4763x; 1.4763x over previous
#include <cuda_runtime.h>
#include <cstdint>
#include <cstddef>
#include <math.h>

// Problem dims
#define BATCH 256
#define Z_DIM 256
#define T_DIM 512
#define ACT_E 256
#define CF    1024
#define N_ACT 64
#define STEPS 64
#define G4    (4*CF)          // 4096

// ---------------- scratch (device globals; no allocation allowed) ----------
__device__ float d_t_rec [BATCH*T_DIM];
__device__ float d_base_a[BATCH*G4];
__device__ float d_base_t[BATCH*G4];
__device__ float d_Ga    [N_ACT*G4];
__device__ float d_Gt    [N_ACT*G4];
__device__ float d_wcol  [G4];
__device__ float d_h_a   [2*BATCH*CF];   // ping-pong by step parity
__device__ float d_h_t   [2*BATCH*CF];
__device__ float d_c_a   [BATCH*CF];
__device__ float d_c_t   [BATCH*CF];
__device__ float d_hid_part[4*BATCH*(CF/2)];
__device__ float d_ts    [BATCH];
__device__ int   d_act   [BATCH];

__device__ __forceinline__ float sigf(float x) { return 1.0f / (1.0f + expf(-x)); }

// ---------------- init --------------------------------------------------
__global__ void init_kernel(const float* __restrict__ Wih_t)
{
    int i = blockIdx.x * blockDim.x + threadIdx.x;
    if (i < 2*BATCH*CF) { d_h_a[i] = 0.f; d_h_t[i] = 0.f; }
    if (i < BATCH*CF)   { d_c_a[i] = 0.f; d_c_t[i] = 0.f; }
    if (i < BATCH) { d_ts[i] = 0.f; d_act[i] = N_ACT - 1; }
    if (i < G4)    { d_wcol[i] = Wih_t[(size_t)i * (T_DIM + ACT_E + 1) + (T_DIM + ACT_E)]; }
}

// ---------------- generic fp32 GEMM (prologue only) ------------------------
template<int BM, int BN, int BK, int TM, int TN>
__global__ void __launch_bounds__((BM/TM)*(BN/TN))
gemm_kernel(const float* __restrict__ A, int lda,
            const float* __restrict__ B, int ldb,
            float* __restrict__ C, int ldc,
            int M, int N, int K,
            const float* __restrict__ bias0, const float* __restrict__ bias1, int relu)
{
    constexpr int THREADS = (BM/TM)*(BN/TN);
    constexpr int AV  = BM*BK/(4*THREADS);
    constexpr int BSC = BN*BK/THREADS;
    static_assert(TM == 4 && (TN % 4) == 0, "tile config");

    __shared__ __align__(16) float As[2][BK][BM];
    __shared__ __align__(16) float Bs[2][BK][BN];

    const int tid = threadIdx.x;
    const int m0  = blockIdx.y * BM;
    const int n0  = blockIdx.x * BN;

    const int tm0 = (tid / (BN/TN)) * TM;
    const int tn0 = (tid % (BN/TN)) * TN;

    float4 ra[AV];
    float  rbs[BSC];
    float  acc[TM][TN];
    #pragma unroll
    for (int i = 0; i < TM; ++i)
        #pragma unroll
        for (int j = 0; j < TN; ++j) acc[i][j] = 0.f;

    const int nt = K / BK;

    // prologue: fetch tile 0
    {
        #pragma unroll
        for (int r = 0; r < AV; ++r) {
            int idx = tid + r*THREADS; int m = idx/(BK/4); int kq = idx%(BK/4);
            ra[r] = *reinterpret_cast<const float4*>(A + (size_t)(m0+m)*lda + kq*4);
        }
        #pragma unroll
        for (int r = 0; r < BSC; ++r) {
            int idx = tid + r*THREADS; int n = idx/BK; int k = idx%BK;
            rbs[r] = B[(size_t)(n0+n)*ldb + k];
        }
        #pragma unroll
        for (int r = 0; r < AV; ++r) {
            int idx = tid + r*THREADS; int m = idx/(BK/4); int kq = idx%(BK/4);
            As[0][kq*4+0][m] = ra[r].x; As[0][kq*4+1][m] = ra[r].y;
            As[0][kq*4+2][m] = ra[r].z; As[0][kq*4+3][m] = ra[r].w;
        }
        #pragma unroll
        for (int r = 0; r < BSC; ++r) {
            int idx = tid + r*THREADS; int n = idx/BK; int k = idx%BK;
            Bs[0][k][n] = rbs[r];
        }
    }
    __syncthreads();

    for (int t = 0; t < nt; ++t) {
        const int cur = t & 1;
        const int nxt = (t + 1) & 1;
        if (t + 1 < nt) {
            const int kk = (t+1)*BK;
            #pragma unroll
            for (int r = 0; r < AV; ++r) {
                int idx = tid + r*THREADS; int m = idx/(BK/4); int kq = idx%(BK/4);
                ra[r] = *reinterpret_cast<const float4*>(A + (size_t)(m0+m)*lda + kk + kq*4);
            }
            #pragma unroll
            for (int r = 0; r < BSC; ++r) {
                int idx = tid + r*THREADS; int n = idx/BK; int k = idx%BK;
                rbs[r] = B[(size_t)(n0+n)*ldb + kk + k];
            }
        }
        #pragma unroll
        for (int k = 0; k < BK; ++k) {
            float a[TM], b[TN];
            *reinterpret_cast<float4*>(a) =
                *reinterpret_cast<const float4*>(&As[cur][k][tm0]);
            #pragma unroll
            for (int q = 0; q < TN/4; ++q)
                *reinterpret_cast<float4*>(&b[q*4]) =
                    *reinterpret_cast<const float4*>(&Bs[cur][k][tn0 + q*4]);
            #pragma unroll
            for (int i = 0; i < TM; ++i)
                #pragma unroll
                for (int j = 0; j < TN; ++j)
                    acc[i][j] = fmaf(a[i], b[j], acc[i][j]);
        }
        if (t + 1 < nt) {
            #pragma unroll
            for (int r = 0; r < AV; ++r) {
                int idx = tid + r*THREADS; int m = idx/(BK/4); int kq = idx%(BK/4);
                As[nxt][kq*4+0][m] = ra[r].x; As[nxt][kq*4+1][m] = ra[r].y;
                As[nxt][kq*4+2][m] = ra[r].z; As[nxt][kq*4+3][m] = ra[r].w;
            }
            #pragma unroll
            for (int r = 0; r < BSC; ++r) {
                int idx = tid + r*THREADS; int n = idx/BK; int k = idx%BK;
                Bs[nxt][k][n] = rbs[r];
            }
        }
        __syncthreads();
    }

    #pragma unroll
    for (int i = 0; i < TM; ++i) {
        const int gm = m0 + tm0 + i;
        #pragma unroll
        for (int j = 0; j < TN; ++j) {
            const int gn = n0 + tn0 + j;
            float v = acc[i][j];
            if (bias0) v += bias0[gn];
            if (bias1) v += bias1[gn];
            if (relu)  v = fmaxf(v, 0.f);
            C[(size_t)gm * ldc + gn] = v;
        }
    }
}

// ---------------- fused LSTM GEMM (mega: A-chain step s+1 + T-chain step s)
// B tile rows interleaved: r = j*4 + gate so each thread's TN=4 accs are
// (i,f,g,o) for one hidden unit j. Epilogue applies base + E-gather (+ ts*wcol)
// and the LSTM pointwise, writing h_out and c in place (elementwise-owned).
// BM=64, BN(r)=128 (32 j x 4 gates), BK=16, TM=4, TN=4, 512 threads.
__global__ void __launch_bounds__(512, 2)
lstm_mega(int nA,
          const float* __restrict__ WhhA, const float* __restrict__ WhhT,
          const float* __restrict__ hA_in, float* __restrict__ hA_out, float* __restrict__ cA,
          const float* __restrict__ baseA, const float* __restrict__ Ga,
          const float* __restrict__ hT_in, float* __restrict__ hT_out, float* __restrict__ cT,
          const float* __restrict__ baseT, const float* __restrict__ Gt,
          const float* __restrict__ tsv, const float* __restrict__ wcol,
          const int* __restrict__ act)
{
    const bool isA = ((int)blockIdx.x) < nA;
    const int  jblk = isA ? blockIdx.x : blockIdx.x - nA;
    const float* Whh  = isA ? WhhA  : WhhT;
    const float* hin  = isA ? hA_in : hT_in;
    float*       hout = isA ? hA_out: hT_out;
    float*       cbuf = isA ? cA    : cT;
    const float* base = isA ? baseA : baseT;
    const float* G    = isA ? Ga    : Gt;

    const int m0    = blockIdx.y * 64;
    const int jBase = jblk * 32;

    __shared__ __align__(16) float As[2][16][68];
    __shared__ __align__(16) float Bs[2][16][132];

    const int tid = threadIdx.x;
    // A staging: one float2 per thread: m = tid/8, kpair = tid%8
    const int am = tid >> 3, akq = tid & 7;
    // B staging: one float4 per thread: r = tid/4, kq = tid%4
    const int br = tid >> 2, bkq = tid & 3;
    const int bj = br >> 2, bg = br & 3;
    const float* Arow = hin + (size_t)(m0 + am) * CF + akq * 2;
    const float* Brow = Whh + (size_t)(bg * CF + jBase + bj) * CF + bkq * 4;

    const int tm0 = (tid >> 5) << 2;       // 0..60
    const int tn0 = (tid & 31) << 2;       // 0..124 (one j = 4 gates)

    float acc[4][4];
    #pragma unroll
    for (int i = 0; i < 4; ++i)
        #pragma unroll
        for (int j = 0; j < 4; ++j) acc[i][j] = 0.f;

    float2 ra; float4 rb;
    // tile 0
    ra = *reinterpret_cast<const float2*>(Arow);
    rb = *reinterpret_cast<const float4*>(Brow);
    As[0][akq*2+0][am] = ra.x; As[0][akq*2+1][am] = ra.y;
    Bs[0][bkq*4+0][br] = rb.x; Bs[0][bkq*4+1][br] = rb.y;
    Bs[0][bkq*4+2][br] = rb.z; Bs[0][bkq*4+3][br] = rb.w;
    __syncthreads();

    const int nt = CF / 16;   // 64
    for (int t = 0; t < nt; ++t) {
        const int cur = t & 1, nxt = cur ^ 1;
        if (t + 1 < nt) {
            ra = *reinterpret_cast<const float2*>(Arow + (t+1)*16);
            rb = *reinterpret_cast<const float4*>(Brow + (t+1)*16);
        }
        #pragma unroll
        for (int k = 0; k < 16; ++k) {
            float a[4], b[4];
            *reinterpret_cast<float4*>(a) = *reinterpret_cast<const float4*>(&As[cur][k][tm0]);
            *reinterpret_cast<float4*>(b) = *reinterpret_cast<const float4*>(&Bs[cur][k][tn0]);
            #pragma unroll
            for (int i = 0; i < 4; ++i)
                #pragma unroll
                for (int j = 0; j < 4; ++j)
                    acc[i][j] = fmaf(a[i], b[j], acc[i][j]);
        }
        if (t + 1 < nt) {
            As[nxt][akq*2+0][am] = ra.x; As[nxt][akq*2+1][am] = ra.y;
            Bs[nxt][bkq*4+0][br] = rb.x; Bs[nxt][bkq*4+1][br] = rb.y;
            Bs[nxt][bkq*4+2][br] = rb.z; Bs[nxt][bkq*4+3][br] = rb.w;
        }
        __syncthreads();
    }

    // ---- fused LSTM epilogue ----
    const int jcol = jBase + (tn0 >> 2);
    float wc0=0.f, wc1=0.f, wc2=0.f, wc3=0.f;
    if (!isA) {
        wc0 = wcol[0*CF + jcol]; wc1 = wcol[1*CF + jcol];
        wc2 = wcol[2*CF + jcol]; wc3 = wcol[3*CF + jcol];
    }
    #pragma unroll
    for (int i = 0; i < 4; ++i) {
        const int m = m0 + tm0 + i;
        const float* brow = base + (size_t)m * G4;
        const float* grow = G + (size_t)act[m] * G4;
        float gi = acc[i][0] + brow[0*CF + jcol] + grow[0*CF + jcol];
        float gf = acc[i][1] + brow[1*CF + jcol] + grow[1*CF + jcol];
        float gg = acc[i][2] + brow[2*CF + jcol] + grow[2*CF + jcol];
        float go = acc[i][3] + brow[3*CF + jcol] + grow[3*CF + jcol];
        if (!isA) {
            const float tm = tsv[m];
            gi += tm * wc0; gf += tm * wc1; gg += tm * wc2; go += tm * wc3;
        }
        const size_t ci = (size_t)m * CF + jcol;
        float cn = sigf(gf) * cbuf[ci] + sigf(gi) * tanhf(gg);
        cbuf[ci] = cn;
        hout[ci] = sigf(go) * tanhf(cn);
    }
}

// ---------------- small fused: logits(s+1) + ts-GEMM partials(s) -----------
__global__ void __launch_bounds__(256)
small_fused(int nLog, int sstep,
            const float* __restrict__ hA,
            const float* __restrict__ W_act, const float* __restrict__ b_act,
            float* __restrict__ out_acts, int* __restrict__ act_idx,
            const float* __restrict__ hT,
            const float* __restrict__ W_ts1, float* __restrict__ hidp)
{
    const int tid = threadIdx.x;
    if ((int)blockIdx.x < nLog) {
        // ---- logits + softmax + argmax, one CTA per batch row ----
        const int row = blockIdx.x;
        __shared__ __align__(16) float sh[CF];
        __shared__ float lg[N_ACT];
        __shared__ float stats[2];
        reinterpret_cast<float4*>(sh)[tid] =
            reinterpret_cast<const float4*>(hA + (size_t)row * CF)[tid];
        __syncthreads();

        const int j = tid >> 2, q = tid & 3;
        const float4* wr = reinterpret_cast<const float4*>(W_act + (size_t)j * CF + q * 256);
        const float4* hr = reinterpret_cast<const float4*>(sh) + q * 64;
        float ssum = 0.f;
        #pragma unroll 8
        for (int i = 0; i < 64; ++i) {
            float4 wv = wr[i], hv = hr[i];
            ssum += wv.x*hv.x + wv.y*hv.y + wv.z*hv.z + wv.w*hv.w;
        }
        ssum += __shfl_down_sync(0xffffffffu, ssum, 2);
        ssum += __shfl_down_sync(0xffffffffu, ssum, 1);
        if (q == 0) lg[j] = ssum + b_act[j];
        __syncthreads();

        if (tid == 0) {
            float mx = lg[0]; int am = 0;
            for (int t = 1; t < N_ACT; ++t) if (lg[t] > mx) { mx = lg[t]; am = t; }
            float sm = 0.f;
            for (int t = 0; t < N_ACT; ++t) sm += expf(lg[t] - mx);
            stats[0] = mx; stats[1] = sm;
            act_idx[row] = am;
        }
        __syncthreads();
        if (tid < N_ACT)
            out_acts[(size_t)row * (STEPS * N_ACT) + sstep * N_ACT + tid] =
                expf(lg[tid] - stats[0]) / stats[1];
    } else {
        // ---- ts first-layer partials: hidp[kz] = hT @ W_ts1^T (split-K 4) --
        const int id = blockIdx.x - nLog;     // 0..127
        const int kz = id >> 5;
        const int rem = id & 31;
        const int n0 = (rem & 7) * 64;        // over CF/2 = 512
        const int mm0 = (rem >> 3) * 64;      // over 256

        const float* A = hT + (size_t)mm0 * CF + kz * 256;
        const float* B = W_ts1 + kz * 256;
        float* C = hidp + (size_t)kz * BATCH * (CF/2);

        __shared__ __align__(16) float SAs[16][68];
        __shared__ __align__(16) float SBs[16][68];

        const int lm = tid >> 2, lkq = tid & 3;  // one float4 each
        const int tm0 = (tid >> 4) << 2;
        const int tn0 = (tid & 15) << 2;

        float acc[4][4];
        #pragma unroll
        for (int i = 0; i < 4; ++i)
            #pragma unroll
            for (int j = 0; j < 4; ++j) acc[i][j] = 0.f;

        for (int t = 0; t < 16; ++t) {
            float4 ra = *reinterpret_cast<const float4*>(A + (size_t)lm * CF + t*16 + lkq*4);
            float4 rb = *reinterpret_cast<const float4*>(B + (size_t)(n0 + lm) * CF + t*16 + lkq*4);
            __syncthreads();
            SAs[lkq*4+0][lm] = ra.x; SAs[lkq*4+1][lm] = ra.y;
            SAs[lkq*4+2][lm] = ra.z; SAs[lkq*4+3][lm] = ra.w;
            SBs[lkq*4+0][lm] = rb.x; SBs[lkq*4+1][lm] = rb.y;
            SBs[lkq*4+2][lm] = rb.z; SBs[lkq*4+3][lm] = rb.w;
            __syncthreads();
            #pragma unroll
            for (int k = 0; k < 16; ++k) {
                float a[4], b[4];
                *reinterpret_cast<float4*>(a) = *reinterpret_cast<const float4*>(&SAs[k][tm0]);
                *reinterpret_cast<float4*>(b) = *reinterpret_cast<const float4*>(&SBs[k][tn0]);
                #pragma unroll
                for (int i = 0; i < 4; ++i)
                    #pragma unroll
                    for (int j = 0; j < 4; ++j)
                        acc[i][j] = fmaf(a[i], b[j], acc[i][j]);
            }
        }
        #pragma unroll
        for (int i = 0; i < 4; ++i)
            #pragma unroll
            for (int j = 0; j < 4; ++j)
                C[(size_t)(mm0 + tm0 + i) * (CF/2) + n0 + tn0 + j] = acc[i][j];
    }
}

// ---------------- ts reduce: combine split-K partials, relu, dot W_ts2 -----
__global__ void tsdot_kernel(const float* __restrict__ part,
                             const float* __restrict__ b1,
                             const float* __restrict__ w2,
                             const float* __restrict__ b2,
                             float* __restrict__ ts,
                             float* __restrict__ out_ts, int s)
{
    const int warp = threadIdx.x >> 5, lane = threadIdx.x & 31;
    const int row = blockIdx.x * 8 + warp;
    const float* p = part + (size_t)row * (CF/2);
    const size_t slice = (size_t)BATCH * (CF/2);
    float acc = 0.f;
    #pragma unroll
    for (int t = 0; t < (CF/2)/32; ++t) {
        int n = lane + t * 32;
        float hv = p[n] + p[slice + n] + p[2*slice + n] + p[3*slice + n] + b1[n];
        hv = fmaxf(hv, 0.f);
        acc += hv * w2[n];
    }
    #pragma unroll
    for (int o = 16; o; o >>= 1) acc += __shfl_down_sync(0xffffffffu, acc, o);
    if (lane == 0) {
        float v = acc + b2[0];
        ts[row] = v;
        out_ts[(size_t)row * STEPS + s] = v;
    }
}

// ---------------- host orchestration ---------------------------------------
static inline float* symf(const void* s) { void* p = nullptr; cudaGetSymbolAddress(&p, s); return (float*)p; }

extern "C" void kernel_launch(void* const* d_in, const int* in_sizes, int n_in,
                              void* d_out, int out_size)
{
    const float* z     = (const float*)d_in[0];
    const float* W_z2t = (const float*)d_in[1];
    const float* b_z2t = (const float*)d_in[2];
    const float* E     = (const float*)d_in[3];
    const float* Wih_a = (const float*)d_in[4];
    const float* Whh_a = (const float*)d_in[5];
    const float* bih_a = (const float*)d_in[6];
    const float* bhh_a = (const float*)d_in[7];
    const float* Wih_t = (const float*)d_in[8];
    const float* Whh_t = (const float*)d_in[9];
    const float* bih_t = (const float*)d_in[10];
    const float* bhh_t = (const float*)d_in[11];
    const float* W_act = (const float*)d_in[12];
    const float* b_act = (const float*)d_in[13];
    const float* W_ts1 = (const float*)d_in[14];
    const float* b_ts1 = (const float*)d_in[15];
    const float* W_ts2 = (const float*)d_in[16];
    const float* b_ts2 = (const float*)d_in[17];

    float* out_acts = (float*)d_out;                              // [B, STEPS, N_ACT]
    float* out_ts   = (float*)d_out + (size_t)BATCH*STEPS*N_ACT;  // [B, STEPS]

    float* t_rec  = symf(d_t_rec);
    float* base_a = symf(d_base_a);
    float* base_t = symf(d_base_t);
    float* Ga     = symf(d_Ga);
    float* Gt     = symf(d_Gt);
    float* wcol   = symf(d_wcol);
    float* h_a    = symf(d_h_a);   // [2][B*CF]
    float* h_t    = symf(d_h_t);
    float* c_a    = symf(d_c_a);
    float* c_t    = symf(d_c_t);
    float* hidp   = symf(d_hid_part);
    float* tsb    = symf(d_ts);
    int*   actb   = (int*)symf(d_act);

    const size_t HP = (size_t)BATCH * CF;   // parity stride for h buffers

    auto g128 = gemm_kernel<64,128,16,4,8>;

    // init state (both h parities zeroed: parity-1 buffer serves as h(-1)=0)
    init_kernel<<<2048, 256>>>(Wih_t);

    // t_rec = relu(z @ W_z2t^T + b_z2t)
    g128<<<dim3(T_DIM/128, BATCH/64), 256>>>(z, Z_DIM, W_z2t, Z_DIM, t_rec, T_DIM,
        BATCH, T_DIM, Z_DIM, b_z2t, nullptr, 1);
    // base_a / base_t = t_rec @ Wih[:, :512]^T + bih + bhh
    g128<<<dim3(G4/128, BATCH/64), 256>>>(t_rec, T_DIM, Wih_a, T_DIM+ACT_E, base_a, G4,
        BATCH, G4, T_DIM, bih_a, bhh_a, 0);
    g128<<<dim3(G4/128, BATCH/64), 256>>>(t_rec, T_DIM, Wih_t, T_DIM+ACT_E+1, base_t, G4,
        BATCH, G4, T_DIM, bih_t, bhh_t, 0);
    // Ga / Gt = E @ Wih[:, 512:768]^T
    g128<<<dim3(G4/128, 1), 256>>>(E, ACT_E, Wih_a + T_DIM, T_DIM+ACT_E, Ga, G4,
        N_ACT, G4, ACT_E, nullptr, nullptr, 0);
    g128<<<dim3(G4/128, 1), 256>>>(E, ACT_E, Wih_t + T_DIM, T_DIM+ACT_E+1, Gt, G4,
        N_ACT, G4, ACT_E, nullptr, nullptr, 0);

    // step 0 A-chain: h_a(0) <- LSTM(h_a(-1)=0, act(-1)=EOT); write parity 0
    lstm_mega<<<dim3(32, 4), 512>>>(32,
        Whh_a, Whh_t,
        h_a + HP, h_a, c_a, base_a, Ga,
        h_t + HP, h_t, c_t, base_t, Gt,   // unused (no T blocks)
        tsb, wcol, actb);
    // logits(0): act(0), out_acts step 0  (grid == nLog, no ts blocks)
    small_fused<<<256, 256>>>(256, 0, h_a, W_act, b_act, out_acts, actb,
                              h_t, W_ts1, hidp);

    for (int s = 0; s < STEPS; ++s) {
        const int pa_in  = s & 1;            // h_a(s) parity
        const int pa_out = (s + 1) & 1;      // h_a(s+1)
        const int pt_in  = (s + 1) & 1;      // h_t(s-1) parity = 1-(s&1)
        const int pt_out = s & 1;            // h_t(s)
        const int nA = (s < STEPS-1) ? 32 : 0;

        // MEGA: gates_a(s+1) [if any] + gates_t(s), LSTM fused in epilogue
        lstm_mega<<<dim3(nA + 32, 4), 512>>>(nA,
            Whh_a, Whh_t,
            h_a + pa_in*HP, h_a + pa_out*HP, c_a, base_a, Ga,
            h_t + pt_in*HP, h_t + pt_out*HP, c_t, base_t, Gt,
            tsb, wcol, actb);

        // SMALL: logits(s+1) [if any] + ts first-layer partials(s)
        const int nLog = (s < STEPS-1) ? 256 : 0;
        small_fused<<<nLog + 128, 256>>>(nLog, s + 1,
            h_a + pa_out*HP, W_act, b_act, out_acts, actb,
            h_t + pt_out*HP, W_ts1, hidp);

        // ts(s) reduce
        tsdot_kernel<<<BATCH/8, 256>>>(hidp, b_ts1, W_ts2, b_ts2, tsb, out_ts, s);
    }
    (void)in_sizes; (void)n_in; (void)out_size;
}

// round 5
// speedup vs baseline: 2.7734x; 1.8786x over previous
#include <cuda_runtime.h>
#include <cuda_bf16.h>
#include <cstdint>
#include <cstddef>
#include <math.h>

// Problem dims
#define BATCH 256
#define Z_DIM 256
#define T_DIM 512
#define ACT_E 256
#define CF    1024
#define N_ACT 64
#define STEPS 64
#define G4    (4*CF)          // 4096

// ---------------- scratch (device globals; no allocation allowed) ----------
__device__ float d_t_rec [BATCH*T_DIM];
__device__ float d_base_a[BATCH*G4];
__device__ float d_base_t[BATCH*G4];
__device__ float d_Ga    [N_ACT*G4];
__device__ float d_Gt    [N_ACT*G4];
__device__ float d_wcol  [G4];
__device__ float d_h_a   [2*BATCH*CF];   // fp32 h ping-pong (read by small_fused)
__device__ float d_h_t   [2*BATCH*CF];
__device__ float d_c_a   [BATCH*CF];
__device__ float d_c_t   [BATCH*CF];
__device__ float d_hid_part[4*BATCH*(CF/2)];
__device__ float d_ts    [BATCH];
__device__ int   d_act   [BATCH];

// Fragment-packed operands for mma.sync m16n8k16 bf16
// B pack: [chain(2)][jblk(32)][nfrag(16)][kstep(64)][lane(32)][4 u32: bhi0,bhi1,blo0,blo1]
__device__ __align__(16) uint32_t d_Bpack[2u*32*16*64*32*4];           // 33.5 MB
// A pack: [parity(2)][mb(16)][kstep(64)][lane(32)][8 u32: ahi0..3, alo0..3]
__device__ __align__(16) uint32_t d_ApA[2][16*64*32*8];                // 2 x 1 MB
__device__ __align__(16) uint32_t d_ApT[2][16*64*32*8];

__device__ __forceinline__ float sigf(float x) { return 1.0f / (1.0f + expf(-x)); }

__device__ __forceinline__ void mma16816(float c[4], const uint32_t a[4], const uint32_t b0, const uint32_t b1)
{
    asm("mma.sync.aligned.m16n8k16.row.col.f32.bf16.bf16.f32 "
        "{%0,%1,%2,%3}, {%4,%5,%6,%7}, {%8,%9}, {%0,%1,%2,%3};"
        : "+f"(c[0]), "+f"(c[1]), "+f"(c[2]), "+f"(c[3])
        : "r"(a[0]), "r"(a[1]), "r"(a[2]), "r"(a[3]), "r"(b0), "r"(b1));
}

// ---------------- init --------------------------------------------------
__global__ void init_kernel(const float* __restrict__ Wih_t)
{
    int i = blockIdx.x * blockDim.x + threadIdx.x;   // 4096*256 = 1,048,576
    if (i < 2*BATCH*CF) { d_h_a[i] = 0.f; d_h_t[i] = 0.f; }
    if (i < BATCH*CF)   { d_c_a[i] = 0.f; d_c_t[i] = 0.f; }
    if (i < 16*64*32*8) { d_ApA[1][i] = 0u; d_ApT[1][i] = 0u; }  // h(-1) = 0
    if (i < BATCH) { d_ts[i] = 0.f; d_act[i] = N_ACT - 1; }
    if (i < G4)    { d_wcol[i] = Wih_t[(size_t)i * (T_DIM + ACT_E + 1) + (T_DIM + ACT_E)]; }
}

// ---------------- pack Whh_a / Whh_t into fragment-major bf16 hi/lo --------
__global__ void pack_whh(const float* __restrict__ Wa, const float* __restrict__ Wt)
{
    size_t idx = (size_t)blockIdx.x * 256 + threadIdx.x;   // 2*4096*1024
    if (idx >= 2ull*G4*CF) return;
    int c = (int)(idx >> 22);
    size_t rem = idx & ((1u<<22) - 1);
    int row = (int)(rem >> 10);       // gate*CF + j
    int k   = (int)(rem & 1023);
    const float* W = c ? Wt : Wa;
    float x = W[(size_t)row * CF + k];
    __nv_bfloat16 hi = __float2bfloat16(x);
    __nv_bfloat16 lo = __float2bfloat16(x - __bfloat162float(hi));

    int gate = row >> 10, j = row & 1023;
    int jb = j >> 5, jloc = j & 31;
    int r = jloc * 4 + gate;          // n within 128-wide tile
    int nf = r >> 3, ncol = r & 7;
    int ks = k >> 4, kin = k & 15;
    int lane = ncol * 4 + ((kin & 7) >> 1);
    int reg  = (kin >> 3) & 1;
    size_t base = ((((size_t)(c*32 + jb)*16 + nf)*64 + ks)*32 + lane)*4;
    char* p = (char*)d_Bpack;
    *(__nv_bfloat16*)(p + (base + reg    )*4 + (kin & 1)*2) = hi;
    *(__nv_bfloat16*)(p + (base + 2 + reg)*4 + (kin & 1)*2) = lo;
}

// ---------------- generic fp32 GEMM (prologue only) ------------------------
template<int BM, int BN, int BK, int TM, int TN>
__global__ void __launch_bounds__((BM/TM)*(BN/TN))
gemm_kernel(const float* __restrict__ A, int lda,
            const float* __restrict__ B, int ldb,
            float* __restrict__ C, int ldc,
            int M, int N, int K,
            const float* __restrict__ bias0, const float* __restrict__ bias1, int relu)
{
    constexpr int THREADS = (BM/TM)*(BN/TN);
    constexpr int AV  = BM*BK/(4*THREADS);
    constexpr int BSC = BN*BK/THREADS;
    static_assert(TM == 4 && (TN % 4) == 0, "tile config");

    __shared__ __align__(16) float As[2][BK][BM];
    __shared__ __align__(16) float Bs[2][BK][BN];

    const int tid = threadIdx.x;
    const int m0  = blockIdx.y * BM;
    const int n0  = blockIdx.x * BN;

    const int tm0 = (tid / (BN/TN)) * TM;
    const int tn0 = (tid % (BN/TN)) * TN;

    float4 ra[AV];
    float  rbs[BSC];
    float  acc[TM][TN];
    #pragma unroll
    for (int i = 0; i < TM; ++i)
        #pragma unroll
        for (int j = 0; j < TN; ++j) acc[i][j] = 0.f;

    const int nt = K / BK;
    {
        #pragma unroll
        for (int r = 0; r < AV; ++r) {
            int idx = tid + r*THREADS; int m = idx/(BK/4); int kq = idx%(BK/4);
            ra[r] = *reinterpret_cast<const float4*>(A + (size_t)(m0+m)*lda + kq*4);
        }
        #pragma unroll
        for (int r = 0; r < BSC; ++r) {
            int idx = tid + r*THREADS; int n = idx/BK; int k = idx%BK;
            rbs[r] = B[(size_t)(n0+n)*ldb + k];
        }
        #pragma unroll
        for (int r = 0; r < AV; ++r) {
            int idx = tid + r*THREADS; int m = idx/(BK/4); int kq = idx%(BK/4);
            As[0][kq*4+0][m] = ra[r].x; As[0][kq*4+1][m] = ra[r].y;
            As[0][kq*4+2][m] = ra[r].z; As[0][kq*4+3][m] = ra[r].w;
        }
        #pragma unroll
        for (int r = 0; r < BSC; ++r) {
            int idx = tid + r*THREADS; int n = idx/BK; int k = idx%BK;
            Bs[0][k][n] = rbs[r];
        }
    }
    __syncthreads();

    for (int t = 0; t < nt; ++t) {
        const int cur = t & 1;
        const int nxt = (t + 1) & 1;
        if (t + 1 < nt) {
            const int kk = (t+1)*BK;
            #pragma unroll
            for (int r = 0; r < AV; ++r) {
                int idx = tid + r*THREADS; int m = idx/(BK/4); int kq = idx%(BK/4);
                ra[r] = *reinterpret_cast<const float4*>(A + (size_t)(m0+m)*lda + kk + kq*4);
            }
            #pragma unroll
            for (int r = 0; r < BSC; ++r) {
                int idx = tid + r*THREADS; int n = idx/BK; int k = idx%BK;
                rbs[r] = B[(size_t)(n0+n)*ldb + kk + k];
            }
        }
        #pragma unroll
        for (int k = 0; k < BK; ++k) {
            float a[TM], b[TN];
            *reinterpret_cast<float4*>(a) =
                *reinterpret_cast<const float4*>(&As[cur][k][tm0]);
            #pragma unroll
            for (int q = 0; q < TN/4; ++q)
                *reinterpret_cast<float4*>(&b[q*4]) =
                    *reinterpret_cast<const float4*>(&Bs[cur][k][tn0 + q*4]);
            #pragma unroll
            for (int i = 0; i < TM; ++i)
                #pragma unroll
                for (int j = 0; j < TN; ++j)
                    acc[i][j] = fmaf(a[i], b[j], acc[i][j]);
        }
        if (t + 1 < nt) {
            #pragma unroll
            for (int r = 0; r < AV; ++r) {
                int idx = tid + r*THREADS; int m = idx/(BK/4); int kq = idx%(BK/4);
                As[nxt][kq*4+0][m] = ra[r].x; As[nxt][kq*4+1][m] = ra[r].y;
                As[nxt][kq*4+2][m] = ra[r].z; As[nxt][kq*4+3][m] = ra[r].w;
            }
            #pragma unroll
            for (int r = 0; r < BSC; ++r) {
                int idx = tid + r*THREADS; int n = idx/BK; int k = idx%BK;
                Bs[nxt][k][n] = rbs[r];
            }
        }
        __syncthreads();
    }

    #pragma unroll
    for (int i = 0; i < TM; ++i) {
        const int gm = m0 + tm0 + i;
        #pragma unroll
        for (int j = 0; j < TN; ++j) {
            const int gn = n0 + tn0 + j;
            float v = acc[i][j];
            if (bias0) v += bias0[gn];
            if (bias1) v += bias1[gn];
            if (relu)  v = fmaxf(v, 0.f);
            C[(size_t)gm * ldc + gn] = v;
        }
    }
}

// ---------------- tensor-core fused LSTM mega kernel ------------------------
// 3-term split-bf16 mma: acc = Ahi*Bhi + Ahi*Blo + Alo*Bhi  (~fp32 accuracy).
// CTA: 256 thr = 8 warps (4 m-bands x 2 n-halves). Tile: 64 rows x 128 gate-cols.
// No smem, no syncthreads: A and B are loaded as pre-packed mma fragments.
// Epilogue: shfl-exchange gates, apply base + E-gather (+ts*wcol) + LSTM
// pointwise; write c, fp32 h, and bf16 hi/lo h in A-fragment layout for the
// next step's GEMM.
__global__ void __launch_bounds__(256)
lstm_mega_mma(int nA,
              const uint32_t* __restrict__ Bp,
              const uint32_t* __restrict__ ApA_in, uint32_t* __restrict__ ApA_out,
              const uint32_t* __restrict__ ApT_in, uint32_t* __restrict__ ApT_out,
              float* __restrict__ hA_out, float* __restrict__ cA,
              const float* __restrict__ baseA, const float* __restrict__ Ga,
              float* __restrict__ hT_out, float* __restrict__ cT,
              const float* __restrict__ baseT, const float* __restrict__ Gt,
              const float* __restrict__ tsv, const float* __restrict__ wcol,
              const int* __restrict__ act)
{
    const bool isA = ((int)blockIdx.x) < nA;
    const int  jblk = isA ? blockIdx.x : blockIdx.x - nA;
    const uint32_t* Ap   = isA ? ApA_in  : ApT_in;
    uint32_t*       ApO  = isA ? ApA_out : ApT_out;
    float*          hout = isA ? hA_out  : hT_out;
    float*          cbuf = isA ? cA      : cT;
    const float*    base = isA ? baseA   : baseT;
    const float*    G    = isA ? Ga      : Gt;

    const int warp = threadIdx.x >> 5, lane = threadIdx.x & 31;
    const int wm = warp >> 1, wn = warp & 1;
    const int mb = blockIdx.y * 4 + wm;                 // 16-row band index

    const uint32_t* aPtr = Ap + (size_t)mb * (64*32*8) + lane * 8;
    const uint32_t* bPtr = Bp + (((size_t)((isA ? 0 : 32) + jblk) * 16 + wn * 8) * 64) * (32*4)
                              + lane * 4;

    float acc[8][4];
    #pragma unroll
    for (int nf = 0; nf < 8; ++nf)
        #pragma unroll
        for (int q = 0; q < 4; ++q) acc[nf][q] = 0.f;

    for (int ks = 0; ks < 64; ++ks) {
        uint4 ah4 = *reinterpret_cast<const uint4*>(aPtr + (size_t)ks * 256);
        uint4 al4 = *reinterpret_cast<const uint4*>(aPtr + (size_t)ks * 256 + 4);
        uint32_t ah[4] = {ah4.x, ah4.y, ah4.z, ah4.w};
        uint32_t al[4] = {al4.x, al4.y, al4.z, al4.w};
        #pragma unroll
        for (int nf = 0; nf < 8; ++nf) {
            uint4 bb = *reinterpret_cast<const uint4*>(bPtr + (size_t)nf * (16*64*32*4/16*16) // nf stride
                                                       );
            // note: nf stride in u32 = 64*32*4 = 8192; ks stride = 32*4 = 128
            bb = *reinterpret_cast<const uint4*>(bPtr + (size_t)nf * 8192 + (size_t)ks * 128);
            mma16816(acc[nf], ah, bb.x, bb.y);   // Ahi * Bhi
            mma16816(acc[nf], ah, bb.z, bb.w);   // Ahi * Blo
            mma16816(acc[nf], al, bb.x, bb.y);   // Alo * Bhi
        }
    }

    // ---- epilogue ----
    const int m1 = blockIdx.y * 64 + wm * 16 + (lane >> 2);
    const bool evenL = ((lane & 1) == 0);
    const int m = evenL ? m1 : m1 + 8;
    const int jBase = jblk * 32 + wn * 16;
    const int actm = act[m];
    const float tsm = isA ? 0.f : tsv[m];
    const float* brow = base + (size_t)m * G4;
    const float* grow = G + (size_t)actm * G4;
    char* aob = (char*)ApO;

    #pragma unroll
    for (int nf = 0; nf < 8; ++nf) {
        float c0 = acc[nf][0], c1 = acc[nf][1], c2 = acc[nf][2], c3 = acc[nf][3];
        float sA = evenL ? c2 : c0;
        float sB = evenL ? c3 : c1;
        float rA = __shfl_xor_sync(0xffffffffu, sA, 1);
        float rB = __shfl_xor_sync(0xffffffffu, sB, 1);
        float gi, gf, gg, go;
        if (evenL) { gi = c0; gf = c1; gg = rA; go = rB; }
        else       { gi = rA; gf = rB; gg = c2; go = c3; }

        const int j = jBase + nf * 2 + ((lane & 3) >> 1);
        gi += brow[0*CF + j] + grow[0*CF + j];
        gf += brow[1*CF + j] + grow[1*CF + j];
        gg += brow[2*CF + j] + grow[2*CF + j];
        go += brow[3*CF + j] + grow[3*CF + j];
        if (!isA) {
            gi += tsm * wcol[0*CF + j];
            gf += tsm * wcol[1*CF + j];
            gg += tsm * wcol[2*CF + j];
            go += tsm * wcol[3*CF + j];
        }
        const size_t ci = (size_t)m * CF + j;
        float cn = sigf(gf) * cbuf[ci] + sigf(gi) * tanhf(gg);
        cbuf[ci] = cn;
        float h = sigf(go) * tanhf(cn);
        hout[ci] = h;

        __nv_bfloat16 hi = __float2bfloat16(h);
        __nv_bfloat16 lo = __float2bfloat16(h - __bfloat162float(hi));
        const int mb2 = m >> 4, rr = m & 15, ks2 = j >> 4, kin = j & 15;
        const int lane2 = (rr & 7) * 4 + ((kin & 7) >> 1);
        const int slot  = ((rr >> 3) & 1) + (((kin >> 3) & 1) << 1);
        const size_t u32i = (((size_t)(mb2 * 64 + ks2) * 32) + lane2) * 8;
        *(__nv_bfloat16*)(aob + (u32i + slot    ) * 4 + (kin & 1) * 2) = hi;
        *(__nv_bfloat16*)(aob + (u32i + 4 + slot) * 4 + (kin & 1) * 2) = lo;
    }
}

// ---------------- small fused: logits(s+1) + ts-GEMM partials(s) -----------
__global__ void __launch_bounds__(256)
small_fused(int nLog, int sstep,
            const float* __restrict__ hA,
            const float* __restrict__ W_act, const float* __restrict__ b_act,
            float* __restrict__ out_acts, int* __restrict__ act_idx,
            const float* __restrict__ hT,
            const float* __restrict__ W_ts1, float* __restrict__ hidp)
{
    const int tid = threadIdx.x;
    if ((int)blockIdx.x < nLog) {
        const int row = blockIdx.x;
        __shared__ __align__(16) float sh[CF];
        __shared__ float lg[N_ACT];
        __shared__ float stats[2];
        reinterpret_cast<float4*>(sh)[tid] =
            reinterpret_cast<const float4*>(hA + (size_t)row * CF)[tid];
        __syncthreads();

        const int j = tid >> 2, q = tid & 3;
        const float4* wr = reinterpret_cast<const float4*>(W_act + (size_t)j * CF + q * 256);
        const float4* hr = reinterpret_cast<const float4*>(sh) + q * 64;
        float ssum = 0.f;
        #pragma unroll 8
        for (int i = 0; i < 64; ++i) {
            float4 wv = wr[i], hv = hr[i];
            ssum += wv.x*hv.x + wv.y*hv.y + wv.z*hv.z + wv.w*hv.w;
        }
        ssum += __shfl_down_sync(0xffffffffu, ssum, 2);
        ssum += __shfl_down_sync(0xffffffffu, ssum, 1);
        if (q == 0) lg[j] = ssum + b_act[j];
        __syncthreads();

        if (tid == 0) {
            float mx = lg[0]; int am = 0;
            for (int t = 1; t < N_ACT; ++t) if (lg[t] > mx) { mx = lg[t]; am = t; }
            float sm = 0.f;
            for (int t = 0; t < N_ACT; ++t) sm += expf(lg[t] - mx);
            stats[0] = mx; stats[1] = sm;
            act_idx[row] = am;
        }
        __syncthreads();
        if (tid < N_ACT)
            out_acts[(size_t)row * (STEPS * N_ACT) + sstep * N_ACT + tid] =
                expf(lg[tid] - stats[0]) / stats[1];
    } else {
        const int id = blockIdx.x - nLog;     // 0..127
        const int kz = id >> 5;
        const int rem = id & 31;
        const int n0 = (rem & 7) * 64;
        const int mm0 = (rem >> 3) * 64;

        const float* A = hT + (size_t)mm0 * CF + kz * 256;
        const float* B = W_ts1 + kz * 256;
        float* C = hidp + (size_t)kz * BATCH * (CF/2);

        __shared__ __align__(16) float SAs[16][68];
        __shared__ __align__(16) float SBs[16][68];

        const int lm = tid >> 2, lkq = tid & 3;
        const int tm0 = (tid >> 4) << 2;
        const int tn0 = (tid & 15) << 2;

        float acc[4][4];
        #pragma unroll
        for (int i = 0; i < 4; ++i)
            #pragma unroll
            for (int j = 0; j < 4; ++j) acc[i][j] = 0.f;

        for (int t = 0; t < 16; ++t) {
            float4 ra = *reinterpret_cast<const float4*>(A + (size_t)lm * CF + t*16 + lkq*4);
            float4 rb = *reinterpret_cast<const float4*>(B + (size_t)(n0 + lm) * CF + t*16 + lkq*4);
            __syncthreads();
            SAs[lkq*4+0][lm] = ra.x; SAs[lkq*4+1][lm] = ra.y;
            SAs[lkq*4+2][lm] = ra.z; SAs[lkq*4+3][lm] = ra.w;
            SBs[lkq*4+0][lm] = rb.x; SBs[lkq*4+1][lm] = rb.y;
            SBs[lkq*4+2][lm] = rb.z; SBs[lkq*4+3][lm] = rb.w;
            __syncthreads();
            #pragma unroll
            for (int k = 0; k < 16; ++k) {
                float a[4], b[4];
                *reinterpret_cast<float4*>(a) = *reinterpret_cast<const float4*>(&SAs[k][tm0]);
                *reinterpret_cast<float4*>(b) = *reinterpret_cast<const float4*>(&SBs[k][tn0]);
                #pragma unroll
                for (int i = 0; i < 4; ++i)
                    #pragma unroll
                    for (int j = 0; j < 4; ++j)
                        acc[i][j] = fmaf(a[i], b[j], acc[i][j]);
            }
        }
        #pragma unroll
        for (int i = 0; i < 4; ++i)
            #pragma unroll
            for (int j = 0; j < 4; ++j)
                C[(size_t)(mm0 + tm0 + i) * (CF/2) + n0 + tn0 + j] = acc[i][j];
    }
}

// ---------------- ts reduce ------------------------------------------------
__global__ void tsdot_kernel(const float* __restrict__ part,
                             const float* __restrict__ b1,
                             const float* __restrict__ w2,
                             const float* __restrict__ b2,
                             float* __restrict__ ts,
                             float* __restrict__ out_ts, int s)
{
    const int warp = threadIdx.x >> 5, lane = threadIdx.x & 31;
    const int row = blockIdx.x * 8 + warp;
    const float* p = part + (size_t)row * (CF/2);
    const size_t slice = (size_t)BATCH * (CF/2);
    float acc = 0.f;
    #pragma unroll
    for (int t = 0; t < (CF/2)/32; ++t) {
        int n = lane + t * 32;
        float hv = p[n] + p[slice + n] + p[2*slice + n] + p[3*slice + n] + b1[n];
        hv = fmaxf(hv, 0.f);
        acc += hv * w2[n];
    }
    #pragma unroll
    for (int o = 16; o; o >>= 1) acc += __shfl_down_sync(0xffffffffu, acc, o);
    if (lane == 0) {
        float v = acc + b2[0];
        ts[row] = v;
        out_ts[(size_t)row * STEPS + s] = v;
    }
}

// ---------------- host orchestration ---------------------------------------
static inline void* symp(const void* s) { void* p = nullptr; cudaGetSymbolAddress(&p, s); return p; }

extern "C" void kernel_launch(void* const* d_in, const int* in_sizes, int n_in,
                              void* d_out, int out_size)
{
    const float* z     = (const float*)d_in[0];
    const float* W_z2t = (const float*)d_in[1];
    const float* b_z2t = (const float*)d_in[2];
    const float* E     = (const float*)d_in[3];
    const float* Wih_a = (const float*)d_in[4];
    const float* Whh_a = (const float*)d_in[5];
    const float* bih_a = (const float*)d_in[6];
    const float* bhh_a = (const float*)d_in[7];
    const float* Wih_t = (const float*)d_in[8];
    const float* Whh_t = (const float*)d_in[9];
    const float* bih_t = (const float*)d_in[10];
    const float* bhh_t = (const float*)d_in[11];
    const float* W_act = (const float*)d_in[12];
    const float* b_act = (const float*)d_in[13];
    const float* W_ts1 = (const float*)d_in[14];
    const float* b_ts1 = (const float*)d_in[15];
    const float* W_ts2 = (const float*)d_in[16];
    const float* b_ts2 = (const float*)d_in[17];

    float* out_acts = (float*)d_out;                              // [B, STEPS, N_ACT]
    float* out_ts   = (float*)d_out + (size_t)BATCH*STEPS*N_ACT;  // [B, STEPS]

    float* t_rec  = (float*)symp(d_t_rec);
    float* base_a = (float*)symp(d_base_a);
    float* base_t = (float*)symp(d_base_t);
    float* Ga     = (float*)symp(d_Ga);
    float* Gt     = (float*)symp(d_Gt);
    float* wcol   = (float*)symp(d_wcol);
    float* h_a    = (float*)symp(d_h_a);
    float* h_t    = (float*)symp(d_h_t);
    float* c_a    = (float*)symp(d_c_a);
    float* c_t    = (float*)symp(d_c_t);
    float* hidp   = (float*)symp(d_hid_part);
    float* tsb    = (float*)symp(d_ts);
    int*   actb   = (int*)symp(d_act);
    uint32_t* Bp  = (uint32_t*)symp(d_Bpack);
    uint32_t* ApA = (uint32_t*)symp(d_ApA);
    uint32_t* ApT = (uint32_t*)symp(d_ApT);

    const size_t HP = (size_t)BATCH * CF;       // fp32 h parity stride
    const size_t AP = (size_t)16*64*32*8;       // packed h parity stride (u32)

    auto g128 = gemm_kernel<64,128,16,4,8>;

    init_kernel<<<4096, 256>>>(Wih_t);
    pack_whh<<<(2*G4*CF)/256, 256>>>(Whh_a, Whh_t);

    // t_rec = relu(z @ W_z2t^T + b_z2t)
    g128<<<dim3(T_DIM/128, BATCH/64), 256>>>(z, Z_DIM, W_z2t, Z_DIM, t_rec, T_DIM,
        BATCH, T_DIM, Z_DIM, b_z2t, nullptr, 1);
    // base_a / base_t = t_rec @ Wih[:, :512]^T + bih + bhh
    g128<<<dim3(G4/128, BATCH/64), 256>>>(t_rec, T_DIM, Wih_a, T_DIM+ACT_E, base_a, G4,
        BATCH, G4, T_DIM, bih_a, bhh_a, 0);
    g128<<<dim3(G4/128, BATCH/64), 256>>>(t_rec, T_DIM, Wih_t, T_DIM+ACT_E+1, base_t, G4,
        BATCH, G4, T_DIM, bih_t, bhh_t, 0);
    // Ga / Gt = E @ Wih[:, 512:768]^T
    g128<<<dim3(G4/128, 1), 256>>>(E, ACT_E, Wih_a + T_DIM, T_DIM+ACT_E, Ga, G4,
        N_ACT, G4, ACT_E, nullptr, nullptr, 0);
    g128<<<dim3(G4/128, 1), 256>>>(E, ACT_E, Wih_t + T_DIM, T_DIM+ACT_E+1, Gt, G4,
        N_ACT, G4, ACT_E, nullptr, nullptr, 0);

    // step 0 A-chain: h_a(0) <- LSTM(h_a(-1)=0, act(-1)=EOT); write parity 0
    lstm_mega_mma<<<dim3(32, 4), 256>>>(32, Bp,
        ApA + AP, ApA, ApT + AP, ApT,
        h_a, c_a, base_a, Ga,
        h_t, c_t, base_t, Gt,
        tsb, wcol, actb);
    // logits(0): act(0), out_acts step 0
    small_fused<<<256, 256>>>(256, 0, h_a, W_act, b_act, out_acts, actb,
                              h_t, W_ts1, hidp);

    for (int s = 0; s < STEPS; ++s) {
        const int pa_in  = s & 1;            // h_a(s) parity
        const int pa_out = (s + 1) & 1;      // h_a(s+1)
        const int pt_in  = (s + 1) & 1;      // h_t(s-1)
        const int pt_out = s & 1;            // h_t(s)
        const int nA = (s < STEPS-1) ? 32 : 0;

        lstm_mega_mma<<<dim3(nA + 32, 4), 256>>>(nA, Bp,
            ApA + pa_in*AP, ApA + pa_out*AP,
            ApT + pt_in*AP, ApT + pt_out*AP,
            h_a + pa_out*HP, c_a, base_a, Ga,
            h_t + pt_out*HP, c_t, base_t, Gt,
            tsb, wcol, actb);

        const int nLog = (s < STEPS-1) ? 256 : 0;
        small_fused<<<nLog + 128, 256>>>(nLog, s + 1,
            h_a + pa_out*HP, W_act, b_act, out_acts, actb,
            h_t + pt_out*HP, W_ts1, hidp);

        tsdot_kernel<<<BATCH/8, 256>>>(hidp, b_ts1, W_ts2, b_ts2, tsb, out_ts, s);
    }
    (void)in_sizes; (void)n_in; (void)out_size;
}